// round 16
// baseline (speedup 1.0000x reference)
#include <cuda_runtime.h>

#define Bsz     32
#define Anch    3
#define Hd      160
#define Wd      160
#define NT      512
#define NCLS    3
#define PLANE   (Hd*Wd)                 // 25600
#define CONF_ELEMS (Bsz*Anch*PLANE)     // 2,457,600
#define PLANE_V4 (PLANE/4)              // 6400

#define NBLOCK  120
#define NTHREAD 320
#define NTH     (NBLOCK*NTHREAD)        // 38400 = 6 * PLANE_V4 (exact cover)
#define NWARPS  (NTHREAD/32)            // 10
#define STRIDE4 307200                  // 6 planes * 51200 float4 per step

__device__ float g_sum;                 // scalar loss accumulator (zero-init)
__device__ unsigned int g_done;

__device__ __forceinline__ float tanh_fast(float x) {
    float y;
    asm("tanh.approx.f32 %0, %1;" : "=f"(y) : "f"(x));
    return y;
}
// sigmoid(x) = 0.5 + 0.5*tanh(0.5x) : one MUFU
__device__ __forceinline__ float sigm(float x) {
    return fmaf(0.5f, tanh_fast(0.5f * x), 0.5f);
}

#define LDG4(dst, ptr)                                                        \
    asm volatile("ld.global.nc.v4.f32 {%0,%1,%2,%3}, [%4];"                   \
                 : "=f"(dst.x), "=f"(dst.y), "=f"(dst.z), "=f"(dst.w)         \
                 : "l"(ptr))

__device__ __forceinline__ unsigned int atomic_inc_acqrel(unsigned int* p) {
    unsigned int old;
    asm volatile("atom.acq_rel.gpu.global.add.u32 %0, [%1], 1;"
                 : "=r"(old) : "l"(p) : "memory");
    return old;
}

// accumulate (1+tanh(x/2))^2 ; caller scales by 0.25 once
__device__ __forceinline__ void usq4(float4 v, float& acc) {
    float u0 = 1.0f + tanh_fast(0.5f * v.x);
    float u1 = 1.0f + tanh_fast(0.5f * v.y);
    float u2 = 1.0f + tanh_fast(0.5f * v.z);
    float u3 = 1.0f + tanh_fast(0.5f * v.w);
    acc = fmaf(u0, u0, acc);
    acc = fmaf(u1, u1, acc);
    acc = fmaf(u2, u2, acc);
    acc = fmaf(u3, u3, acc);
}

__global__ void __launch_bounds__(NTHREAD)
detection_loss_kernel(const float* __restrict__ pred,
                      const float* __restrict__ targets,
                      float* __restrict__ out)
{
    const int tid = blockIdx.x * NTHREAD + threadIdx.x;

    float acc[6] = {0.f, 0.f, 0.f, 0.f, 0.f, 0.f};
    // [0]=conf_sumsq [1]=conf_corr [2]=box [3]=cls [4]=unused [5]=valid-count

    // ---- every block independently counts valid targets (global n) ----
    // Each thread checks targets threadIdx.x, threadIdx.x+320 (<512).
    {
        float c = 0.f;
        for (int i = threadIdx.x; i < NT; i += NTHREAD) {
            float tb = targets[i*6 + 0];
            float tx = targets[i*6 + 2];
            float ty = targets[i*6 + 3];
            int b  = (int)tb;
            int gx = (int)(tx * (float)Wd);
            int gy = (int)(ty * (float)Hd);
            if (gx >= 0 && gx < Wd && gy >= 0 && gy < Hd && b >= 0 && b < Bsz)
                c += 1.f;
        }
        acc[5] = c;
    }

    // ---- dense pass: 16 constant-stride float4 loads, exact cover ----
    {
        const int q = tid / PLANE_V4;            // 0..5  (one div total)
        const int r = tid - q * PLANE_V4;        // 0..6399
        const float4* p = reinterpret_cast<const float4*>(pred)
                        + (size_t)(51200 * q + 25600 + r);

        float4 x0,x1,x2,x3,x4,x5,x6,x7,x8,x9,xa,xb,xc,xd,xe,xf;
        LDG4(x0, p);               LDG4(x1, p + 1*STRIDE4);
        LDG4(x2, p + 2*STRIDE4);   LDG4(x3, p + 3*STRIDE4);
        LDG4(x4, p + 4*STRIDE4);   LDG4(x5, p + 5*STRIDE4);
        LDG4(x6, p + 6*STRIDE4);   LDG4(x7, p + 7*STRIDE4);
        LDG4(x8, p + 8*STRIDE4);   LDG4(x9, p + 9*STRIDE4);
        LDG4(xa, p + 10*STRIDE4);  LDG4(xb, p + 11*STRIDE4);
        LDG4(xc, p + 12*STRIDE4);  LDG4(xd, p + 13*STRIDE4);
        LDG4(xe, p + 14*STRIDE4);  LDG4(xf, p + 15*STRIDE4);

        float s = 0.f;
        usq4(x0, s); usq4(x1, s); usq4(x2, s); usq4(x3, s);
        usq4(x4, s); usq4(x5, s); usq4(x6, s); usq4(x7, s);
        usq4(x8, s); usq4(x9, s); usq4(xa, s); usq4(xb, s);
        usq4(xc, s); usq4(xd, s); usq4(xe, s); usq4(xf, s);
        acc[0] = 0.25f * s;
    }

    // ---- sparse pass: one item per (target, anchor); 1536 items ----
    if (tid < NT * Anch) {
        int t = tid / Anch;
        int a = tid - t * Anch;
        float tc = targets[t*6 + 1];
        float tx = targets[t*6 + 2];
        float ty = targets[t*6 + 3];
        float tw = targets[t*6 + 4];
        float th = targets[t*6 + 5];
        int b  = (int)targets[t*6 + 0];
        int c  = (int)tc;
        int gx = (int)(tx * (float)Wd);
        int gy = (int)(ty * (float)Hd);
        if (gx >= 0 && gx < Wd && gy >= 0 && gy < Hd && b >= 0 && b < Bsz) {
            const float* base = pred + (size_t)(b * 24 + a * 8) * PLANE
                                     + (size_t)gy * Wd + gx;
            float p0 = base[0*PLANE];
            float p1 = base[1*PLANE];
            float p2 = base[2*PLANE];
            float p3 = base[3*PLANE];
            float p4v = base[4*PLANE];
            float p5 = base[5*PLANE];
            float p6 = base[6*PLANE];
            float p7 = base[7*PLANE];

            float bx = sigm(p0) - tx;
            float by = sigm(p1) - ty;
            float bw = __expf(p2) - tw;
            float bh = __expf(p3) - th;
            acc[2] = bx*bx + by*by + bw*bw + bh*bh;

            acc[1] = 1.0f - 2.0f * sigm(p4v);        // (s-1)^2 - s^2

            float t0 = (c == 0) ? 1.0f : 0.0f;
            float t1 = (c == 1) ? 1.0f : 0.0f;
            float t2 = (c == 2) ? 1.0f : 0.0f;
            float d0 = sigm(p5) - t0;
            float d1 = sigm(p6) - t1;
            float d2 = sigm(p7) - t2;
            acc[3] = d0*d0 + d1*d1 + d2*d2;
        }
    }

    // ---- block reduction: warp shuffles, then shared (5 live slots) ----
    #pragma unroll
    for (int o = 16; o > 0; o >>= 1) {
        acc[0] += __shfl_down_sync(0xFFFFFFFFu, acc[0], o);
        acc[1] += __shfl_down_sync(0xFFFFFFFFu, acc[1], o);
        acc[2] += __shfl_down_sync(0xFFFFFFFFu, acc[2], o);
        acc[3] += __shfl_down_sync(0xFFFFFFFFu, acc[3], o);
        acc[5] += __shfl_down_sync(0xFFFFFFFFu, acc[5], o);
    }

    __shared__ float sh[NWARPS][5];
    int wid = threadIdx.x >> 5;
    int lid = threadIdx.x & 31;
    if (lid == 0) {
        sh[wid][0] = acc[0]; sh[wid][1] = acc[1]; sh[wid][2] = acc[2];
        sh[wid][3] = acc[3]; sh[wid][4] = acc[5];
    }
    __syncthreads();

    if (threadIdx.x == 0) {
        float tot[5] = {0.f, 0.f, 0.f, 0.f, 0.f};
        #pragma unroll
        for (int w = 0; w < NWARPS; w++)
            #pragma unroll
            for (int i = 0; i < 5; i++) tot[i] += sh[w][i];

        // this block's scalar loss contribution (n known locally)
        float n = 3.0f * tot[4];                       // anchors per valid target
        float inv_n = __fdividef(1.0f, n);
        float contrib = (tot[0] + tot[1]) * (1.0f / (float)CONF_ELEMS)
                      + 1.25f * tot[2] * inv_n                  // 5 * box/(4n)
                      + tot[3] * inv_n * (1.0f / (float)NCLS);  // cls/(3n)

        atomicAdd(&g_sum, contrib);                    // relaxed, L2-coherent
        unsigned int old = atomic_inc_acqrel(&g_done); // release my add, acquire others'
        if (old == (unsigned)(NBLOCK - 1)) {
            float s = atomicAdd(&g_sum, 0.0f);         // atomic read at LTS
            out[0] = s;
            g_sum  = 0.0f;                             // reset for next replay
            g_done = 0u;
        }
    }
}

extern "C" void kernel_launch(void* const* d_in, const int* in_sizes, int n_in,
                              void* d_out, int out_size)
{
    const float* pred    = (const float*)d_in[0];
    const float* targets = (const float*)d_in[1];
    float* out = (float*)d_out;
    detection_loss_kernel<<<NBLOCK, NTHREAD>>>(pred, targets, out);
}